// round 1
// baseline (speedup 1.0000x reference)
#include <cuda_runtime.h>
#include <cuda_bf16.h>
#include <math.h>

// Problem constants
#define BB 1024
#define SS 512
#define DD 768
#define H1 256
#define H2 64
#define NC 4
#define FEAT (3 * DD)   // 2304

// Scratch: feat matrix (B, 3D) = 1024 x 2304 floats = 9.4 MB
__device__ float g_feat[(size_t)BB * FEAT];

// ---------------------------------------------------------------------------
// Kernel 1: span means + cls -> g_feat
// One block per batch, 192 threads, each thread owns one float4 column group
// (768 floats per row = 192 float4). Rows are 3072B contiguous -> coalesced.
// ---------------------------------------------------------------------------
__global__ void __launch_bounds__(192) span_feat_kernel(
    const float* __restrict__ x,
    const int* __restrict__ e1_span,
    const int* __restrict__ e2_span)
{
    const int b = blockIdx.x;
    const int t = threadIdx.x;   // 0..191

    const float4* xb = reinterpret_cast<const float4*>(x + (size_t)b * SS * DD);

    const int lo1 = e1_span[2 * b];
    const int hi1 = max(e1_span[2 * b + 1], lo1 + 1);
    const int lo2 = e2_span[2 * b];
    const int hi2 = max(e2_span[2 * b + 1], lo2 + 1);

    float4 s1 = make_float4(0.f, 0.f, 0.f, 0.f);
    for (int r = lo1; r < hi1; ++r) {
        float4 v = xb[(size_t)r * (DD / 4) + t];
        s1.x += v.x; s1.y += v.y; s1.z += v.z; s1.w += v.w;
    }
    float4 s2 = make_float4(0.f, 0.f, 0.f, 0.f);
    for (int r = lo2; r < hi2; ++r) {
        float4 v = xb[(size_t)r * (DD / 4) + t];
        s2.x += v.x; s2.y += v.y; s2.z += v.z; s2.w += v.w;
    }

    const float inv1 = 1.0f / (float)(hi1 - lo1);
    const float inv2 = 1.0f / (float)(hi2 - lo2);
    float4 cls = xb[t];  // row 0

    float4* fb = reinterpret_cast<float4*>(g_feat + (size_t)b * FEAT);
    fb[t]            = make_float4(s1.x * inv1, s1.y * inv1, s1.z * inv1, s1.w * inv1);
    fb[DD / 4 + t]   = make_float4(s2.x * inv2, s2.y * inv2, s2.z * inv2, s2.w * inv2);
    fb[DD / 2 + t]   = cls;
}

// ---------------------------------------------------------------------------
// Kernel 2: fused MLP + softmax for 4 batches per block (256 threads).
// h1: each thread owns one of 256 outputs, 4 batch accumulators.
// W1[k][n] reads are coalesced across threads; feat broadcast from smem.
// ---------------------------------------------------------------------------
#define MB 4

__global__ void __launch_bounds__(256) mlp_kernel(
    const float* __restrict__ W1, const float* __restrict__ b1,
    const float* __restrict__ W2, const float* __restrict__ b2,
    const float* __restrict__ W3, const float* __restrict__ b3,
    float* __restrict__ out)
{
    __shared__ float sfeat[MB][FEAT];   // 36 KB
    __shared__ float sh1[MB][H1];       // 4 KB
    __shared__ float sh2[MB][H2];       // 1 KB
    __shared__ float slog[MB][NC];

    const int t = threadIdx.x;          // 0..255
    const int b0 = blockIdx.x * MB;

    // Load feat tile (MB*FEAT = 9216 floats = 2304 float4)
    {
        const float4* gf = reinterpret_cast<const float4*>(g_feat + (size_t)b0 * FEAT);
        float4* sf = reinterpret_cast<float4*>(&sfeat[0][0]);
        #pragma unroll
        for (int i = 0; i < (MB * FEAT / 4) / 256; ++i)
            sf[t + i * 256] = gf[t + i * 256];
    }
    __syncthreads();

    // Layer 1: (MB,2304) @ (2304,256) + relu
    {
        const float bias = b1[t];
        float a0 = bias, a1 = bias, a2 = bias, a3 = bias;
        #pragma unroll 8
        for (int k = 0; k < FEAT; ++k) {
            const float w = W1[(size_t)k * H1 + t];
            a0 = fmaf(w, sfeat[0][k], a0);
            a1 = fmaf(w, sfeat[1][k], a1);
            a2 = fmaf(w, sfeat[2][k], a2);
            a3 = fmaf(w, sfeat[3][k], a3);
        }
        sh1[0][t] = fmaxf(a0, 0.f);
        sh1[1][t] = fmaxf(a1, 0.f);
        sh1[2][t] = fmaxf(a2, 0.f);
        sh1[3][t] = fmaxf(a3, 0.f);
    }
    __syncthreads();

    // Layer 2: (MB,256) @ (256,64) + relu. thread = mb*64 + n
    {
        const int mb = t >> 6;
        const int n = t & 63;
        float a = b2[n];
        #pragma unroll 8
        for (int k = 0; k < H1; ++k)
            a = fmaf(sh1[mb][k], W2[k * H2 + n], a);
        sh2[mb][n] = fmaxf(a, 0.f);
    }
    __syncthreads();

    // Layer 3: (MB,64) @ (64,4). thread = mb*4 + n, 16 active
    if (t < MB * NC) {
        const int mb = t >> 2;
        const int n = t & 3;
        float a = b3[n];
        #pragma unroll
        for (int k = 0; k < H2; ++k)
            a = fmaf(sh2[mb][k], W3[k * NC + n], a);
        slog[mb][n] = a;
    }
    __syncthreads();

    // Softmax over 4 classes; thread mb < 4 handles one batch row
    if (t < MB) {
        const int mb = t;
        float l0 = slog[mb][0], l1 = slog[mb][1], l2 = slog[mb][2], l3 = slog[mb][3];
        float m = fmaxf(fmaxf(l0, l1), fmaxf(l2, l3));
        float e0 = __expf(l0 - m), e1 = __expf(l1 - m);
        float e2 = __expf(l2 - m), e3 = __expf(l3 - m);
        float inv = 1.0f / (e0 + e1 + e2 + e3);
        float* o = out + (size_t)(b0 + mb) * NC;
        o[0] = e0 * inv; o[1] = e1 * inv; o[2] = e2 * inv; o[3] = e3 * inv;
    }
}

// ---------------------------------------------------------------------------
// Launch
// Inputs (metadata order): x, e1_span, e2_span, W1, b1, W2, b2, W3, b3
// ---------------------------------------------------------------------------
extern "C" void kernel_launch(void* const* d_in, const int* in_sizes, int n_in,
                              void* d_out, int out_size)
{
    const float* x  = (const float*)d_in[0];
    const int* e1   = (const int*)d_in[1];
    const int* e2   = (const int*)d_in[2];
    const float* W1 = (const float*)d_in[3];
    const float* b1 = (const float*)d_in[4];
    const float* W2 = (const float*)d_in[5];
    const float* b2 = (const float*)d_in[6];
    const float* W3 = (const float*)d_in[7];
    const float* b3 = (const float*)d_in[8];
    float* out      = (float*)d_out;

    span_feat_kernel<<<BB, 192>>>(x, e1, e2);
    mlp_kernel<<<BB / MB, 256>>>(W1, b1, W2, b2, W3, b3, out);
}

// round 2
// speedup vs baseline: 1.8017x; 1.8017x over previous
#include <cuda_runtime.h>
#include <cuda_bf16.h>
#include <math.h>

// Problem constants
#define BB 1024
#define SS 512
#define DD 768
#define H1 256
#define H2 64
#define NC 4
#define FEAT (3 * DD)   // 2304
#define KS 4            // K-split for layer 1
#define KCH (FEAT / KS) // 576
#define MB 4            // batches per layer-1 block

// Scratch
__device__ float g_feat[(size_t)BB * FEAT];                 // 9.4 MB
__device__ float g_part[(size_t)KS * (BB / MB) * MB * H1];  // 4 MB

// ---------------------------------------------------------------------------
// Kernel 1: span means + cls -> g_feat
// One block per (batch, span). 384 threads = 192 cols x 2 row-strides.
// Span 0 block also writes the cls row.
// ---------------------------------------------------------------------------
__global__ void __launch_bounds__(384) span_feat_kernel(
    const float* __restrict__ x,
    const int* __restrict__ e1_span,
    const int* __restrict__ e2_span)
{
    __shared__ float4 sred[192];

    const int b    = blockIdx.x;
    const int span = blockIdx.y;          // 0 or 1
    const int col  = threadIdx.x;         // 0..191
    const int half = threadIdx.y;         // 0..1

    const float4* xb = reinterpret_cast<const float4*>(x + (size_t)b * SS * DD);

    const int* sp = (span == 0) ? e1_span : e2_span;
    const int lo = sp[2 * b];
    const int hi = max(sp[2 * b + 1], lo + 1);

    float4 s = make_float4(0.f, 0.f, 0.f, 0.f);
    #pragma unroll 4
    for (int r = lo + half; r < hi; r += 2) {
        float4 v = xb[(size_t)r * (DD / 4) + col];
        s.x += v.x; s.y += v.y; s.z += v.z; s.w += v.w;
    }

    if (half == 1) sred[col] = s;
    __syncthreads();

    if (half == 0) {
        float4 o = sred[col];
        const float inv = 1.0f / (float)(hi - lo);
        o.x = (s.x + o.x) * inv;
        o.y = (s.y + o.y) * inv;
        o.z = (s.z + o.z) * inv;
        o.w = (s.w + o.w) * inv;

        float4* fb = reinterpret_cast<float4*>(g_feat + (size_t)b * FEAT);
        fb[span * (DD / 4) + col] = o;
        if (span == 0) {
            fb[DD / 2 + col] = xb[col];   // cls = row 0
        }
    }
}

// ---------------------------------------------------------------------------
// Kernel 2a: layer-1 partial GEMM with K-split.
// grid = (B/MB, KS) = (256, 4), block 256. Each block: 4 batches x 576 k's.
// Partial sums -> g_part[ks][bg][mb][t].
// ---------------------------------------------------------------------------
__global__ void __launch_bounds__(256) l1_partial_kernel(
    const float* __restrict__ W1)
{
    __shared__ float sfeat[MB][KCH];   // 9 KB

    const int t  = threadIdx.x;        // 0..255 -> n
    const int bg = blockIdx.x;         // 0..255
    const int ks = blockIdx.y;         // 0..3

    // Load feat chunk: MB rows x KCH cols
    {
        const float* gf = g_feat + (size_t)(bg * MB) * FEAT + ks * KCH;
        #pragma unroll
        for (int mb = 0; mb < MB; ++mb) {
            // KCH=576 floats = 144 float4 -> 256 threads, some idle per pass
            for (int i = t; i < KCH / 4; i += 256) {
                reinterpret_cast<float4*>(&sfeat[mb][0])[i] =
                    reinterpret_cast<const float4*>(gf + (size_t)mb * FEAT)[i];
            }
        }
    }
    __syncthreads();

    const float* w = W1 + (size_t)(ks * KCH) * H1 + t;
    float a0 = 0.f, a1 = 0.f, a2 = 0.f, a3 = 0.f;
    #pragma unroll 8
    for (int k = 0; k < KCH; ++k) {
        const float wv = w[(size_t)k * H1];
        a0 = fmaf(wv, sfeat[0][k], a0);
        a1 = fmaf(wv, sfeat[1][k], a1);
        a2 = fmaf(wv, sfeat[2][k], a2);
        a3 = fmaf(wv, sfeat[3][k], a3);
    }

    float* gp = g_part + (size_t)((ks * (BB / MB) + bg) * MB) * H1 + t;
    gp[0 * H1] = a0;
    gp[1 * H1] = a1;
    gp[2 * H1] = a2;
    gp[3 * H1] = a3;
}

// ---------------------------------------------------------------------------
// Kernel 2b: finish. One block per batch (1024 blocks, 256 threads).
// Sum K-split partials + bias + relu -> layer 2 -> layer 3 -> softmax.
// ---------------------------------------------------------------------------
__global__ void __launch_bounds__(256) mlp_finish_kernel(
    const float* __restrict__ b1,
    const float* __restrict__ W2, const float* __restrict__ b2,
    const float* __restrict__ W3, const float* __restrict__ b3,
    float* __restrict__ out)
{
    __shared__ float sh1[H1];
    __shared__ float spart[4][H2];
    __shared__ float sh2[H2];
    __shared__ float slog[NC];

    const int t  = threadIdx.x;
    const int b  = blockIdx.x;
    const int bg = b >> 2;
    const int mb = b & 3;

    // h1 = relu(b1 + sum_ks part)
    {
        const float* gp = g_part + (size_t)(bg * MB + mb) * H1 + t;
        const size_t stride = (size_t)(BB / MB) * MB * H1;
        float a = b1[t];
        #pragma unroll
        for (int ks = 0; ks < KS; ++ks)
            a += gp[ks * stride];
        sh1[t] = fmaxf(a, 0.f);
    }
    __syncthreads();

    // Layer 2: 256 threads = 64 n x 4 k-quarters
    {
        const int n = t & 63;
        const int q = t >> 6;
        float a = 0.f;
        #pragma unroll 8
        for (int k = q * 64; k < (q + 1) * 64; ++k)
            a = fmaf(sh1[k], W2[k * H2 + n], a);
        spart[q][n] = a;
    }
    __syncthreads();
    if (t < H2) {
        float a = b2[t] + spart[0][t] + spart[1][t] + spart[2][t] + spart[3][t];
        sh2[t] = fmaxf(a, 0.f);
    }
    __syncthreads();

    // Layer 3: 4 warps, warp n computes logit n via shuffle reduce
    if (t < 128) {
        const int n    = t >> 5;
        const int lane = t & 31;
        float a = sh2[lane] * W3[lane * NC + n]
                + sh2[lane + 32] * W3[(lane + 32) * NC + n];
        #pragma unroll
        for (int off = 16; off > 0; off >>= 1)
            a += __shfl_down_sync(0xFFFFFFFF, a, off);
        if (lane == 0) slog[n] = a + b3[n];
    }
    __syncthreads();

    // Softmax (one thread)
    if (t == 0) {
        float l0 = slog[0], l1 = slog[1], l2 = slog[2], l3 = slog[3];
        float m = fmaxf(fmaxf(l0, l1), fmaxf(l2, l3));
        float e0 = __expf(l0 - m), e1 = __expf(l1 - m);
        float e2 = __expf(l2 - m), e3 = __expf(l3 - m);
        float inv = 1.0f / (e0 + e1 + e2 + e3);
        float* o = out + (size_t)b * NC;
        o[0] = e0 * inv; o[1] = e1 * inv; o[2] = e2 * inv; o[3] = e3 * inv;
    }
}

// ---------------------------------------------------------------------------
// Launch
// Inputs: x, e1_span, e2_span, W1, b1, W2, b2, W3, b3
// ---------------------------------------------------------------------------
extern "C" void kernel_launch(void* const* d_in, const int* in_sizes, int n_in,
                              void* d_out, int out_size)
{
    const float* x  = (const float*)d_in[0];
    const int* e1   = (const int*)d_in[1];
    const int* e2   = (const int*)d_in[2];
    const float* W1 = (const float*)d_in[3];
    const float* b1 = (const float*)d_in[4];
    const float* W2 = (const float*)d_in[5];
    const float* b2 = (const float*)d_in[6];
    const float* W3 = (const float*)d_in[7];
    const float* b3 = (const float*)d_in[8];
    float* out      = (float*)d_out;

    dim3 g1(BB, 2);
    dim3 t1(192, 2);
    span_feat_kernel<<<g1, t1>>>(x, e1, e2);

    dim3 g2(BB / MB, KS);
    l1_partial_kernel<<<g2, 256>>>(W1);

    mlp_finish_kernel<<<BB, 256>>>(b1, W2, b2, W3, b3, out);
}

// round 5
// speedup vs baseline: 2.0049x; 1.1128x over previous
#include <cuda_runtime.h>
#include <cuda_bf16.h>
#include <math.h>

// Problem constants
#define BB 1024
#define SS 512
#define DD 768
#define H1 256
#define H2 64
#define NC 4
#define FEAT (3 * DD)    // 2304
#define KS 8             // K-split for layer 1
#define KCH (FEAT / KS)  // 288
#define MB 16            // batches per layer-1 block

// Scratch
__device__ float g_feat[(size_t)BB * FEAT];     // 9.4 MB
__device__ float g_part[(size_t)KS * BB * H1];  // 8 MB

// ---------------------------------------------------------------------------
// Kernel 1: span means + cls -> g_feat, reading the span UNION once when the
// spans overlap. grid (B, 2) x block (96, 4): 96 float4 cols x 4 row-strides.
// Overlap case decomposes into 3 contiguous segments with block-uniform
// ownership -> three plain loops, no per-iteration predication.
// ---------------------------------------------------------------------------
__global__ void __launch_bounds__(384) span_feat_kernel(
    const float* __restrict__ x,
    const int* __restrict__ e1_span,
    const int* __restrict__ e2_span)
{
    __shared__ float4 s1p[4][96];
    __shared__ float4 s2p[4][96];

    const int b   = blockIdx.x;
    const int col = threadIdx.x + blockIdx.y * 96;  // float4 col 0..191
    const int ty  = threadIdx.y;                    // 0..3

    const float4* xb = reinterpret_cast<const float4*>(x + (size_t)b * SS * DD);

    const int lo1 = e1_span[2 * b];
    const int hi1 = max(e1_span[2 * b + 1], lo1 + 1);
    const int lo2 = e2_span[2 * b];
    const int hi2 = max(e2_span[2 * b + 1], lo2 + 1);

    const int olo = max(lo1, lo2);
    const int ohi = min(hi1, hi2);

    float4 s1 = make_float4(0.f, 0.f, 0.f, 0.f);
    float4 s2 = make_float4(0.f, 0.f, 0.f, 0.f);

    if (olo < ohi) {
        // Overlap: union = [mlo, mhi) = segA [mlo,olo) + segB [olo,ohi) + segC [ohi,mhi)
        const int mlo = min(lo1, lo2);
        const int mhi = max(hi1, hi2);

        float4 sA = make_float4(0.f, 0.f, 0.f, 0.f);
        float4 sB = make_float4(0.f, 0.f, 0.f, 0.f);
        float4 sC = make_float4(0.f, 0.f, 0.f, 0.f);

        for (int r = mlo + ty; r < olo; r += 4) {
            float4 v = xb[(size_t)r * (DD / 4) + col];
            sA.x += v.x; sA.y += v.y; sA.z += v.z; sA.w += v.w;
        }
        for (int r = olo + ty; r < ohi; r += 4) {
            float4 v = xb[(size_t)r * (DD / 4) + col];
            sB.x += v.x; sB.y += v.y; sB.z += v.z; sB.w += v.w;
        }
        for (int r = ohi + ty; r < mhi; r += 4) {
            float4 v = xb[(size_t)r * (DD / 4) + col];
            sC.x += v.x; sC.y += v.y; sC.z += v.z; sC.w += v.w;
        }

        // segA belongs to the span that starts earlier; segC to the one
        // ending later (subset relations hold because the spans overlap).
        const float a1 = (lo1 < lo2) ? 1.f : 0.f;
        const float a2 = (lo2 < lo1) ? 1.f : 0.f;
        const float c1 = (hi1 > hi2) ? 1.f : 0.f;
        const float c2 = (hi2 > hi1) ? 1.f : 0.f;

        s1.x = sB.x + a1 * sA.x + c1 * sC.x;
        s1.y = sB.y + a1 * sA.y + c1 * sC.y;
        s1.z = sB.z + a1 * sA.z + c1 * sC.z;
        s1.w = sB.w + a1 * sA.w + c1 * sC.w;
        s2.x = sB.x + a2 * sA.x + c2 * sC.x;
        s2.y = sB.y + a2 * sA.y + c2 * sC.y;
        s2.z = sB.z + a2 * sA.z + c2 * sC.z;
        s2.w = sB.w + a2 * sA.w + c2 * sC.w;
    } else {
        for (int r = lo1 + ty; r < hi1; r += 4) {
            float4 v = xb[(size_t)r * (DD / 4) + col];
            s1.x += v.x; s1.y += v.y; s1.z += v.z; s1.w += v.w;
        }
        for (int r = lo2 + ty; r < hi2; r += 4) {
            float4 v = xb[(size_t)r * (DD / 4) + col];
            s2.x += v.x; s2.y += v.y; s2.z += v.z; s2.w += v.w;
        }
    }

    s1p[ty][threadIdx.x] = s1;
    s2p[ty][threadIdx.x] = s2;
    __syncthreads();

    float4* fb = reinterpret_cast<float4*>(g_feat + (size_t)b * FEAT);

    if (ty == 0) {
        const float inv1 = 1.0f / (float)(hi1 - lo1);
        float4 a = s1p[0][threadIdx.x], bq = s1p[1][threadIdx.x];
        float4 c = s1p[2][threadIdx.x], d  = s1p[3][threadIdx.x];
        fb[col] = make_float4((a.x + bq.x + c.x + d.x) * inv1,
                              (a.y + bq.y + c.y + d.y) * inv1,
                              (a.z + bq.z + c.z + d.z) * inv1,
                              (a.w + bq.w + c.w + d.w) * inv1);
    } else if (ty == 1) {
        const float inv2 = 1.0f / (float)(hi2 - lo2);
        float4 a = s2p[0][threadIdx.x], bq = s2p[1][threadIdx.x];
        float4 c = s2p[2][threadIdx.x], d  = s2p[3][threadIdx.x];
        fb[DD / 4 + col] = make_float4((a.x + bq.x + c.x + d.x) * inv2,
                                       (a.y + bq.y + c.y + d.y) * inv2,
                                       (a.z + bq.z + c.z + d.z) * inv2,
                                       (a.w + bq.w + c.w + d.w) * inv2);
    } else if (ty == 2) {
        fb[DD / 2 + col] = xb[col];   // cls = row 0
    }
}

// ---------------------------------------------------------------------------
// Kernel 2a: layer-1 partial GEMM, K-split, register-tiled 4n x 4mb.
// grid (B/MB, KS) = (64, 8), block 256.
// ---------------------------------------------------------------------------
__global__ void __launch_bounds__(256) l1_partial_kernel(
    const float* __restrict__ W1)
{
    __shared__ float sfeat[MB][KCH];   // 18 KB

    const int t   = threadIdx.x;
    const int bg  = blockIdx.x;        // 0..63
    const int ks  = blockIdx.y;        // 0..7
    const int n0  = (t & 63) * 4;
    const int mb0 = (t >> 6) * 4;

    // Stage feat chunk: MB rows x KCH cols = 1152 float4
    {
        const float* gf = g_feat + (size_t)(bg * MB) * FEAT + ks * KCH;
        for (int idx = t; idx < MB * (KCH / 4); idx += 256) {
            const int mb = idx / (KCH / 4);
            const int i  = idx - mb * (KCH / 4);
            reinterpret_cast<float4*>(&sfeat[mb][0])[i] =
                reinterpret_cast<const float4*>(gf + (size_t)mb * FEAT)[i];
        }
    }
    __syncthreads();

    float4 acc[4];
    #pragma unroll
    for (int i = 0; i < 4; ++i) acc[i] = make_float4(0.f, 0.f, 0.f, 0.f);

    const float4* w = reinterpret_cast<const float4*>(
        W1 + (size_t)(ks * KCH) * H1 + n0);

    #pragma unroll 2
    for (int k = 0; k < KCH; ++k) {
        const float4 wv = __ldg(&w[(size_t)k * (H1 / 4)]);
        const float f0 = sfeat[mb0 + 0][k];
        const float f1 = sfeat[mb0 + 1][k];
        const float f2 = sfeat[mb0 + 2][k];
        const float f3 = sfeat[mb0 + 3][k];
        acc[0].x = fmaf(wv.x, f0, acc[0].x); acc[0].y = fmaf(wv.y, f0, acc[0].y);
        acc[0].z = fmaf(wv.z, f0, acc[0].z); acc[0].w = fmaf(wv.w, f0, acc[0].w);
        acc[1].x = fmaf(wv.x, f1, acc[1].x); acc[1].y = fmaf(wv.y, f1, acc[1].y);
        acc[1].z = fmaf(wv.z, f1, acc[1].z); acc[1].w = fmaf(wv.w, f1, acc[1].w);
        acc[2].x = fmaf(wv.x, f2, acc[2].x); acc[2].y = fmaf(wv.y, f2, acc[2].y);
        acc[2].z = fmaf(wv.z, f2, acc[2].z); acc[2].w = fmaf(wv.w, f2, acc[2].w);
        acc[3].x = fmaf(wv.x, f3, acc[3].x); acc[3].y = fmaf(wv.y, f3, acc[3].y);
        acc[3].z = fmaf(wv.z, f3, acc[3].z); acc[3].w = fmaf(wv.w, f3, acc[3].w);
    }

    // g_part[ks][bg*MB + mb][n]
    float* gp = g_part + ((size_t)ks * BB + bg * MB + mb0) * H1 + n0;
    #pragma unroll
    for (int i = 0; i < 4; ++i)
        *reinterpret_cast<float4*>(gp + (size_t)i * H1) = acc[i];
}

// ---------------------------------------------------------------------------
// Kernel 2b: finish. One block per batch (1024 blocks, 256 threads).
// ---------------------------------------------------------------------------
__global__ void __launch_bounds__(256) mlp_finish_kernel(
    const float* __restrict__ b1,
    const float* __restrict__ W2, const float* __restrict__ b2,
    const float* __restrict__ W3, const float* __restrict__ b3,
    float* __restrict__ out)
{
    __shared__ float sh1[H1];
    __shared__ float spart[4][H2];
    __shared__ float sh2[H2];
    __shared__ float slog[NC];

    const int t = threadIdx.x;
    const int b = blockIdx.x;

    // h1 = relu(b1 + sum_ks part)
    {
        const float* gp = g_part + (size_t)b * H1 + t;
        float a = b1[t];
        #pragma unroll
        for (int ks = 0; ks < KS; ++ks)
            a += gp[(size_t)ks * BB * H1];
        sh1[t] = fmaxf(a, 0.f);
    }
    __syncthreads();

    // Layer 2: 256 threads = 64 n x 4 k-quarters
    {
        const int n = t & 63;
        const int q = t >> 6;
        float a = 0.f;
        #pragma unroll 8
        for (int k = q * 64; k < (q + 1) * 64; ++k)
            a = fmaf(sh1[k], W2[k * H2 + n], a);
        spart[q][n] = a;
    }
    __syncthreads();
    if (t < H2) {
        float a = b2[t] + spart[0][t] + spart[1][t] + spart[2][t] + spart[3][t];
        sh2[t] = fmaxf(a, 0.f);
    }
    __syncthreads();

    // Layer 3: 4 warps, warp n computes logit n via shuffle reduce
    if (t < 128) {
        const int n    = t >> 5;
        const int lane = t & 31;
        float a = sh2[lane] * W3[lane * NC + n]
                + sh2[lane + 32] * W3[(lane + 32) * NC + n];
        #pragma unroll
        for (int off = 16; off > 0; off >>= 1)
            a += __shfl_down_sync(0xFFFFFFFF, a, off);
        if (lane == 0) slog[n] = a + b3[n];
    }
    __syncthreads();

    if (t == 0) {
        float l0 = slog[0], l1 = slog[1], l2 = slog[2], l3 = slog[3];
        float m = fmaxf(fmaxf(l0, l1), fmaxf(l2, l3));
        float e0 = __expf(l0 - m), e1 = __expf(l1 - m);
        float e2 = __expf(l2 - m), e3 = __expf(l3 - m);
        float inv = 1.0f / (e0 + e1 + e2 + e3);
        float* o = out + (size_t)b * NC;
        o[0] = e0 * inv; o[1] = e1 * inv; o[2] = e2 * inv; o[3] = e3 * inv;
    }
}

// ---------------------------------------------------------------------------
// Launch
// Inputs: x, e1_span, e2_span, W1, b1, W2, b2, W3, b3
// ---------------------------------------------------------------------------
extern "C" void kernel_launch(void* const* d_in, const int* in_sizes, int n_in,
                              void* d_out, int out_size)
{
    const float* x  = (const float*)d_in[0];
    const int* e1   = (const int*)d_in[1];
    const int* e2   = (const int*)d_in[2];
    const float* W1 = (const float*)d_in[3];
    const float* b1 = (const float*)d_in[4];
    const float* W2 = (const float*)d_in[5];
    const float* b2 = (const float*)d_in[6];
    const float* W3 = (const float*)d_in[7];
    const float* b3 = (const float*)d_in[8];
    float* out      = (float*)d_out;

    dim3 g1(BB, 2);
    dim3 t1(96, 4);
    span_feat_kernel<<<g1, t1>>>(x, e1, e2);

    dim3 g2(BB / MB, KS);
    l1_partial_kernel<<<g2, 256>>>(W1);

    mlp_finish_kernel<<<BB, 256>>>(b1, W2, b2, W3, b3, out);
}